// round 11
// baseline (speedup 1.0000x reference)
#include <cuda_runtime.h>
#include <cstdint>

#define B_ 4
#define H_ 16
#define T_ 2048
#define K_ 64
#define CH_ 128
#define N_ 16
#define BH_ (B_*H_)
#define OUT_ELEMS (B_*H_*T_*K_)
#define LOGMIN (-5.2983174324035645f)

// ---- scratch ----
__device__ float g_rwi[B_*H_*T_*K_];      // r * exp(cum_prev)  (tf32-rounded)
__device__ float g_wkv[BH_*N_*K_*K_];
__device__ float g_wsl[BH_*N_*K_];        // ws (log-domain chunk decay sums)

// ---- phase1 smem layout (float offsets) ----
#define O_RW    0        // 128 x 64, stride 68 (8704); after MMA1 reused as partial buf
#define O_CUM   8704     // 128 x 64, stride 64 (8192)
#define O_KK    16896    // 128 x 64, stride 76 (9728)
#define O_V     26624    // 128 x 64, stride 72 (9216)
#define O_U     35840
#define O_DIAG  35904    // 128
#define O_EWS   36032    // 64
#define O_SEG   36096    // 8 x 64
#define SMEM1_FLOATS 36608
#define SMEM1_BYTES  (SMEM1_FLOATS*4)

__device__ __forceinline__ float f2tf(float x) {
    uint32_t r;
    asm("cvt.rna.tf32.f32 %0, %1;" : "=r"(r) : "f"(x));
    return __uint_as_float(r);
}
__device__ __forceinline__ void mma1688(float* c, uint32_t a0, uint32_t a1, uint32_t a2, uint32_t a3,
                                        uint32_t b0, uint32_t b1) {
    asm volatile("mma.sync.aligned.m16n8k8.row.col.f32.tf32.tf32.f32 "
                 "{%0,%1,%2,%3},{%4,%5,%6,%7},{%8,%9},{%0,%1,%2,%3};"
                 : "+f"(c[0]), "+f"(c[1]), "+f"(c[2]), "+f"(c[3])
                 : "r"(a0), "r"(a1), "r"(a2), "r"(a3), "r"(b0), "r"(b1));
}
#define FB(x) __float_as_uint(x)

// ======================= phase 1 (round-6/8 best version) =======================
__global__ void __launch_bounds__(512)
rwkv_phase1(const float* __restrict__ r, const float* __restrict__ k,
            const float* __restrict__ v, const float* __restrict__ w,
            const float* __restrict__ u, float* __restrict__ out)
{
    extern __shared__ float sm[];
    const int tid = threadIdx.x;
    const int wid = tid >> 5, lid = tid & 31;
    const int ly = lid >> 2, lx = lid & 3;
    const int bhn = blockIdx.x;
    const int bh = bhn >> 4, n = bhn & 15;
    const int h = bh & (H_ - 1);
    const int base = bh * (T_ * K_) + n * (CH_ * K_);

    float4 pr[4], pk[4];
    {
        const float4* r4g = (const float4*)(r + base);
        const float4* k4g = (const float4*)(k + base);
        #pragma unroll
        for (int it = 0; it < 4; ++it) {
            pr[it] = r4g[tid + it * 512];
            pk[it] = k4g[tid + it * 512];
        }
    }

    {
        const float4* w4 = (const float4*)(w + base);
        const float4* v4 = (const float4*)(v + base);
        #pragma unroll
        for (int it = 0; it < 4; ++it) {
            int f4 = tid + it * 512;
            int t = f4 >> 4, k0 = (f4 & 15) * 4;
            float4 ww = w4[f4];
            ww.x = fmaxf(ww.x, LOGMIN); ww.y = fmaxf(ww.y, LOGMIN);
            ww.z = fmaxf(ww.z, LOGMIN); ww.w = fmaxf(ww.w, LOGMIN);
            *(float4*)&sm[O_CUM + t * 64 + k0] = ww;
            float4 vv = v4[f4];
            vv.x = f2tf(vv.x); vv.y = f2tf(vv.y); vv.z = f2tf(vv.z); vv.w = f2tf(vv.w);
            *(float4*)&sm[O_V + t * 72 + k0] = vv;
        }
        if (tid < 64) sm[O_U + tid] = u[h * 64 + tid];
    }
    __syncthreads();

    {
        int kq = tid & 63, seg = tid >> 6;
        float run = 0.f;
        #pragma unroll
        for (int tt = 0; tt < 16; ++tt) {
            int idx = (seg * 16 + tt) * 64 + kq;
            run += sm[O_CUM + idx];
            sm[O_CUM + idx] = run;
        }
        sm[O_SEG + seg * 64 + kq] = run;
    }
    __syncthreads();

    {
        int kq = tid & 63, seg = tid >> 6;
        if (seg > 0) {
            float pre = 0.f;
            #pragma unroll
            for (int s = 0; s < 7; ++s)
                if (s < seg) pre += sm[O_SEG + s * 64 + kq];
            #pragma unroll
            for (int tt = 0; tt < 16; ++tt) sm[O_CUM + (seg * 16 + tt) * 64 + kq] += pre;
        } else {
            float ws = 0.f;
            #pragma unroll
            for (int s = 0; s < 8; ++s) ws += sm[O_SEG + s * 64 + kq];
            sm[O_EWS + kq] = __expf(ws);
            g_wsl[(bh * N_ + n) * K_ + kq] = ws;     // log-domain for inter kernel
        }
    }
    __syncthreads();

    {
        #pragma unroll
        for (int it = 0; it < 4; ++it) {
            int f4 = tid + it * 512;
            int t = f4 >> 4, k0 = (f4 & 15) * 4;
            float4 rv = pr[it];
            float4 kv = pk[it];
            float4 c4 = *(const float4*)&sm[O_CUM + t * 64 + k0];
            float4 cp4 = (t > 0) ? *(const float4*)&sm[O_CUM + (t - 1) * 64 + k0]
                                 : make_float4(0.f, 0.f, 0.f, 0.f);
            float4 uu = *(const float4*)&sm[O_U + k0];
            float re[4] = {rv.x, rv.y, rv.z, rv.w};
            float ke[4] = {kv.x, kv.y, kv.z, kv.w};
            float ce[4] = {c4.x, c4.y, c4.z, c4.w};
            float cpe[4] = {cp4.x, cp4.y, cp4.z, cp4.w};
            float ue[4] = {uu.x, uu.y, uu.z, uu.w};
            float rwv[4], kkv[4];
            float dpart = 0.f;
            #pragma unroll
            for (int e = 0; e < 4; ++e) {
                rwv[e] = f2tf(re[e] * __expf(cpe[e]));
                kkv[e] = f2tf(ke[e] * __expf(-ce[e]));
                dpart += re[e] * ue[e] * ke[e];
            }
            *(float4*)&sm[O_RW + t * 68 + k0] = make_float4(rwv[0], rwv[1], rwv[2], rwv[3]);
            *(float4*)&sm[O_KK + t * 76 + k0] = make_float4(kkv[0], kkv[1], kkv[2], kkv[3]);
            *(float4*)&g_rwi[base + f4 * 4]   = make_float4(rwv[0], rwv[1], rwv[2], rwv[3]);
            float dv = dpart;
            #pragma unroll
            for (int s = 1; s < 16; s <<= 1) dv += __shfl_xor_sync(0xffffffffu, dv, s, 16);
            if ((tid & 15) == 0) sm[O_DIAG + t] = dv;
        }
    }
    __syncthreads();

    const int jh = wid >> 3;
    const int widL = wid & 7;
    const int blk = (widL < 4) ? widL : 11 - widL;
    const int i0 = blk * 16;
    int ntmax = (i0 + 16 - jh * 64) >> 3;
    ntmax = ntmax < 0 ? 0 : (ntmax > 8 ? 8 : ntmax);

    float c1[8][4];
    #pragma unroll
    for (int nt = 0; nt < 8; ++nt)
        #pragma unroll
        for (int e = 0; e < 4; ++e) c1[nt][e] = 0.f;

    #pragma unroll
    for (int ks = 0; ks < 8; ++ks) {
        int k0 = ks * 8;
        const float* ar = &sm[O_RW + (i0 + ly) * 68 + k0 + lx];
        uint32_t a0 = FB(ar[0]), a1 = FB(ar[8 * 68]), a2 = FB(ar[4]), a3 = FB(ar[8 * 68 + 4]);
        #pragma unroll
        for (int nt = 0; nt < 8; ++nt) {
            if (nt < ntmax) {
                const float* br = &sm[O_KK + (jh * 64 + nt * 8 + ly) * 76 + k0 + lx];
                mma1688(c1[nt], a0, a1, a2, a3, FB(br[0]), FB(br[4]));
            }
        }
    }

    {
        const int i0k = (wid & 3) * 16, j0c = (wid >> 2) * 16;
        float c3[2][4];
        #pragma unroll
        for (int nt = 0; nt < 2; ++nt)
            #pragma unroll
            for (int e = 0; e < 4; ++e) c3[nt][e] = 0.f;
        #pragma unroll
        for (int ks = 0; ks < 16; ++ks) {
            int k0 = ks * 8;
            const float* ac = &sm[O_KK + (k0 + lx) * 76 + i0k + ly];
            uint32_t a0 = FB(ac[0]), a1 = FB(ac[8]), a2 = FB(ac[4 * 76]), a3 = FB(ac[4 * 76 + 8]);
            #pragma unroll
            for (int nt = 0; nt < 2; ++nt) {
                const float* br = &sm[O_V + (k0 + lx) * 72 + j0c + nt * 8 + ly];
                mma1688(c3[nt], a0, a1, a2, a3, FB(br[0]), FB(br[4 * 72]));
            }
        }
        int wb = bhn * (K_ * K_);
        int il = i0k + ly, ih = il + 8;
        float sl = sm[O_EWS + il], sh = sm[O_EWS + ih];
        #pragma unroll
        for (int nt = 0; nt < 2; ++nt) {
            int jb = j0c + nt * 8 + 2 * lx;
            *(float2*)&g_wkv[wb + il * 64 + jb] = make_float2(c3[nt][0] * sl, c3[nt][1] * sl);
            *(float2*)&g_wkv[wb + ih * 64 + jb] = make_float2(c3[nt][2] * sh, c3[nt][3] * sh);
        }
    }
    __syncthreads();

    float c2[8][4];
    #pragma unroll
    for (int nt = 0; nt < 8; ++nt)
        #pragma unroll
        for (int e = 0; e < 4; ++e) c2[nt][e] = 0.f;

    {
        const int il = i0 + ly, ih = il + 8;
        const int l1 = ly * 4 + (lx >> 1);
        const int l2 = l1 + 2;
        const bool odd = lx & 1;
        #pragma unroll
        for (int nt = 0; nt < 8; ++nt) {
            if (nt < ntmax) {
                int jc = jh * 64 + nt * 8;
                int jcg = jc + 2 * lx;
                float m0 = (jcg     < il) ? f2tf(c1[nt][0]) : 0.f;
                float m1 = (jcg + 1 < il) ? f2tf(c1[nt][1]) : 0.f;
                float m2 = (jcg     < ih) ? f2tf(c1[nt][2]) : 0.f;
                float m3 = (jcg + 1 < ih) ? f2tf(c1[nt][3]) : 0.f;
                float t00 = __shfl_sync(0xffffffffu, m0, l1);
                float t01 = __shfl_sync(0xffffffffu, m1, l1);
                float t20 = __shfl_sync(0xffffffffu, m0, l2);
                float t21 = __shfl_sync(0xffffffffu, m1, l2);
                float t10 = __shfl_sync(0xffffffffu, m2, l1);
                float t11 = __shfl_sync(0xffffffffu, m3, l1);
                float t30 = __shfl_sync(0xffffffffu, m2, l2);
                float t31 = __shfl_sync(0xffffffffu, m3, l2);
                uint32_t a0 = FB(odd ? t01 : t00);
                uint32_t a2 = FB(odd ? t21 : t20);
                uint32_t a1 = FB(odd ? t11 : t10);
                uint32_t a3 = FB(odd ? t31 : t30);
                #pragma unroll
                for (int no = 0; no < 8; ++no) {
                    const float* br = &sm[O_V + (jc + lx) * 72 + no * 8 + ly];
                    mma1688(c2[no], a0, a1, a2, a3, FB(br[0]), FB(br[4 * 72]));
                }
            }
        }
    }

    if (jh == 1 && ntmax > 0) {
        float* pb = &sm[O_RW + (blk - 4) * 1088];
        int jb = 2 * lx;
        #pragma unroll
        for (int nt = 0; nt < 8; ++nt) {
            *(float2*)&pb[ly * 68 + nt * 8 + jb]       = make_float2(c2[nt][0], c2[nt][1]);
            *(float2*)&pb[(ly + 8) * 68 + nt * 8 + jb] = make_float2(c2[nt][2], c2[nt][3]);
        }
    }
    __syncthreads();

    if (jh == 0) {
        const int il = i0 + ly, ih = il + 8;
        const float dgl = sm[O_DIAG + il], dgh = sm[O_DIAG + ih];
        const bool haveP = (blk >= 4);
        const float* pb = &sm[O_RW + (blk - 4) * 1088];
        #pragma unroll
        for (int nt = 0; nt < 8; ++nt) {
            int jb = nt * 8 + 2 * lx;
            float2 pl = make_float2(0.f, 0.f), ph = make_float2(0.f, 0.f);
            if (haveP) {
                pl = *(const float2*)&pb[ly * 68 + jb];
                ph = *(const float2*)&pb[(ly + 8) * 68 + jb];
            }
            float2 vl = *(const float2*)&sm[O_V + il * 72 + jb];
            float2 vh = *(const float2*)&sm[O_V + ih * 72 + jb];
            float o0 = c2[nt][0] + pl.x + dgl * vl.x;
            float o1 = c2[nt][1] + pl.y + dgl * vl.y;
            float o2 = c2[nt][2] + ph.x + dgh * vh.x;
            float o3 = c2[nt][3] + ph.y + dgh * vh.y;
            *(float2*)&out[base + il * 64 + jb] = make_float2(o0, o1);
            *(float2*)&out[base + ih * 64 + jb] = make_float2(o2, o3);
        }
    }
}

// ============ inter kernel: closed-form state per (bh, chunk), no serial scan ============
// grid 1024 (bh x chunk), 256 threads.
#define I_RW   0        // 128 x 64, stride 68 (8704)
#define I_ST   8704     // 64 x 64, stride 72 (4608), tf32 state
#define I_WGT  13312    // 16 x 64 (wgt[m][k])
#define I_W0   14336    // 64 : exp(W_n)
#define I_E15  14400    // 64 : exp(ws_15)
#define INTER_FLOATS 14464
#define INTER_BYTES (INTER_FLOATS*4)

__global__ void __launch_bounds__(256)
rwkv_inter(const float* __restrict__ state0, float* __restrict__ out,
           float* __restrict__ outF)
{
    extern __shared__ float sm[];
    const int tid = threadIdx.x;
    const int wid = tid >> 5, lid = tid & 31;
    const int ly = lid >> 2, lx = lid & 3;
    const int bhn = blockIdx.x;
    const int bh = bhn >> 4, n = bhn & 15;
    const int base = bh * (T_ * K_) + n * (CH_ * K_);

    // stage rw chunk into smem
    {
        const float4* rw4 = (const float4*)(g_rwi + base);
        #pragma unroll
        for (int it = 0; it < 8; ++it) {
            int f4 = tid + it * 256;
            int t = f4 >> 4, k0 = (f4 & 15) * 4;
            *(float4*)&sm[I_RW + t * 68 + k0] = rw4[f4];
        }
    }

    // weights: tid<64, one k column each
    if (tid < 64) {
        const int kk = tid;
        float wsv[16];
        #pragma unroll
        for (int j = 0; j < 16; ++j) wsv[j] = g_wsl[(bh * N_ + j) * K_ + kk];
        float W = 0.f;
        #pragma unroll
        for (int j = 0; j < 16; ++j) if (j < n) W += wsv[j];
        float p = 0.f;
        #pragma unroll
        for (int m = 0; m < 16; ++m) {
            if (m < n) {
                p += wsv[m];
                sm[I_WGT + m * 64 + kk] = __expf(W - p);
            }
        }
        sm[I_W0 + kk] = __expf(W);
        sm[I_E15 + kk] = __expf(wsv[15]);
    }
    __syncthreads();

    // state accumulation: thread -> k = tid>>2, v = (tid&3)*16 .. +15
    const int kk = tid >> 2;
    const int v0 = (tid & 3) * 16;
    {
        float s[16];
        const float w0 = sm[I_W0 + kk];
        const float* s0p = &state0[bh * (K_ * K_) + kk * 64 + v0];
        #pragma unroll
        for (int q = 0; q < 4; ++q) {
            float4 sv = *(const float4*)&s0p[q * 4];
            s[q*4+0] = sv.x * w0; s[q*4+1] = sv.y * w0;
            s[q*4+2] = sv.z * w0; s[q*4+3] = sv.w * w0;
        }
        const float* wbase = g_wkv + bh * N_ * (K_ * K_) + kk * 64 + v0;
        for (int m = 0; m < n; ++m) {
            float wg = sm[I_WGT + m * 64 + kk];
            const float* wp = wbase + m * (K_ * K_);
            #pragma unroll
            for (int q = 0; q < 4; ++q) {
                float4 wv = *(const float4*)&wp[q * 4];
                s[q*4+0] = fmaf(wv.x, wg, s[q*4+0]);
                s[q*4+1] = fmaf(wv.y, wg, s[q*4+1]);
                s[q*4+2] = fmaf(wv.z, wg, s[q*4+2]);
                s[q*4+3] = fmaf(wv.w, wg, s[q*4+3]);
            }
        }
        // n==15 block also produces the final state (exact)
        if (n == 15) {
            float e15 = sm[I_E15 + kk];
            const float* wp = wbase + 15 * (K_ * K_);
            float* fp = &outF[bh * (K_ * K_) + kk * 64 + v0];
            #pragma unroll
            for (int q = 0; q < 4; ++q) {
                float4 wv = *(const float4*)&wp[q * 4];
                float4 fo;
                fo.x = fmaf(s[q*4+0], e15, wv.x);
                fo.y = fmaf(s[q*4+1], e15, wv.y);
                fo.z = fmaf(s[q*4+2], e15, wv.z);
                fo.w = fmaf(s[q*4+3], e15, wv.w);
                *(float4*)&fp[q * 4] = fo;
            }
        }
        // write tf32 state to smem (B operand layout)
        #pragma unroll
        for (int q = 0; q < 4; ++q) {
            float4 sv = make_float4(f2tf(s[q*4+0]), f2tf(s[q*4+1]),
                                    f2tf(s[q*4+2]), f2tf(s[q*4+3]));
            *(float4*)&sm[I_ST + kk * 72 + v0 + q * 4] = sv;
        }
    }
    __syncthreads();

    // MMA: warp wid -> rows i0..i0+15, all 64 cols
    const int i0 = wid * 16;
    const int il = i0 + ly, ih = il + 8;

    // prefetch out tile (RMW) early
    float2 o_l[8], o_h[8];
    float* ob = out + base;
    #pragma unroll
    for (int nt = 0; nt < 8; ++nt) {
        int jb = nt * 8 + 2 * lx;
        o_l[nt] = *(const float2*)&ob[il * 64 + jb];
        o_h[nt] = *(const float2*)&ob[ih * 64 + jb];
    }

    float c[8][4];
    #pragma unroll
    for (int nt = 0; nt < 8; ++nt)
        #pragma unroll
        for (int e = 0; e < 4; ++e) c[nt][e] = 0.f;

    #pragma unroll
    for (int ks = 0; ks < 8; ++ks) {
        int k0 = ks * 8;
        const float* ar = &sm[I_RW + (i0 + ly) * 68 + k0 + lx];
        uint32_t a0 = FB(ar[0]), a1 = FB(ar[8 * 68]), a2 = FB(ar[4]), a3 = FB(ar[8 * 68 + 4]);
        #pragma unroll
        for (int nt = 0; nt < 8; ++nt) {
            const float* br = &sm[I_ST + (k0 + lx) * 72 + nt * 8 + ly];
            mma1688(c[nt], a0, a1, a2, a3, FB(br[0]), FB(br[4 * 72]));
        }
    }

    #pragma unroll
    for (int nt = 0; nt < 8; ++nt) {
        int jb = nt * 8 + 2 * lx;
        o_l[nt].x += c[nt][0]; o_l[nt].y += c[nt][1];
        o_h[nt].x += c[nt][2]; o_h[nt].y += c[nt][3];
        *(float2*)&ob[il * 64 + jb] = o_l[nt];
        *(float2*)&ob[ih * 64 + jb] = o_h[nt];
    }
}

extern "C" void kernel_launch(void* const* d_in, const int* in_sizes, int n_in,
                              void* d_out, int out_size)
{
    (void)in_sizes; (void)n_in; (void)out_size;
    const float* r  = (const float*)d_in[0];
    const float* k  = (const float*)d_in[1];
    const float* v  = (const float*)d_in[2];
    const float* w  = (const float*)d_in[3];
    const float* u  = (const float*)d_in[4];
    const float* s0 = (const float*)d_in[5];
    float* out  = (float*)d_out;
    float* outF = out + OUT_ELEMS;

    cudaFuncSetAttribute(rwkv_phase1, cudaFuncAttributeMaxDynamicSharedMemorySize, SMEM1_BYTES);
    cudaFuncSetAttribute(rwkv_inter, cudaFuncAttributeMaxDynamicSharedMemorySize, INTER_BYTES);

    rwkv_phase1<<<BH_ * N_, 512, SMEM1_BYTES>>>(r, k, v, w, u, out);
    rwkv_inter<<<BH_ * N_, 256, INTER_BYTES>>>(s0, out, outF);
}

// round 12
// speedup vs baseline: 1.0729x; 1.0729x over previous
#include <cuda_runtime.h>
#include <cuda_fp16.h>
#include <cstdint>

#define B_ 4
#define H_ 16
#define T_ 2048
#define K_ 64
#define CH_ 128
#define N_ 16
#define BH_ (B_*H_)
#define OUT_ELEMS (B_*H_*T_*K_)
#define LOGMIN (-5.2983174324035645f)

// ---- scratch ----
__device__ __half g_rwi[B_*H_*T_*K_];     // r * exp(cum_prev)  (fp16)
__device__ float g_wkv[BH_*N_*K_*K_];
__device__ float g_wse[BH_*N_*K_];

// ---- phase1 smem layout (float offsets) ----
#define O_RW    0        // 128 x 64, stride 68 (8704); after MMA1 reused as partial buf
#define O_CUM   8704     // 128 x 64, stride 64 (8192)
#define O_KK    16896    // 128 x 64, stride 76 (9728)
#define O_V     26624    // 128 x 64, stride 72 (9216)
#define O_U     35840
#define O_DIAG  35904    // 128
#define O_EWS   36032    // 64
#define O_SEG   36096    // 8 x 64
#define SMEM1_FLOATS 36608
#define SMEM1_BYTES  (SMEM1_FLOATS*4)

__device__ __forceinline__ float f2tf(float x) {
    uint32_t r;
    asm("cvt.rna.tf32.f32 %0, %1;" : "=r"(r) : "f"(x));
    return __uint_as_float(r);
}
__device__ __forceinline__ uint32_t packh2(float a, float b) {
    __half2 h = __floats2half2_rn(a, b);
    return *(uint32_t*)&h;
}
__device__ __forceinline__ void mma1688(float* c, uint32_t a0, uint32_t a1, uint32_t a2, uint32_t a3,
                                        uint32_t b0, uint32_t b1) {
    asm volatile("mma.sync.aligned.m16n8k8.row.col.f32.tf32.tf32.f32 "
                 "{%0,%1,%2,%3},{%4,%5,%6,%7},{%8,%9},{%0,%1,%2,%3};"
                 : "+f"(c[0]), "+f"(c[1]), "+f"(c[2]), "+f"(c[3])
                 : "r"(a0), "r"(a1), "r"(a2), "r"(a3), "r"(b0), "r"(b1));
}
#define FB(x) __float_as_uint(x)

// ======================= phase 1 =======================
__global__ void __launch_bounds__(512)
rwkv_phase1(const float* __restrict__ r, const float* __restrict__ k,
            const float* __restrict__ v, const float* __restrict__ w,
            const float* __restrict__ u, float* __restrict__ out)
{
    extern __shared__ float sm[];
    const int tid = threadIdx.x;
    const int wid = tid >> 5, lid = tid & 31;
    const int ly = lid >> 2, lx = lid & 3;
    const int bhn = blockIdx.x;
    const int bh = bhn >> 4, n = bhn & 15;
    const int h = bh & (H_ - 1);
    const int base = bh * (T_ * K_) + n * (CH_ * K_);

    float4 pr[4], pk[4];
    {
        const float4* r4g = (const float4*)(r + base);
        const float4* k4g = (const float4*)(k + base);
        #pragma unroll
        for (int it = 0; it < 4; ++it) {
            pr[it] = r4g[tid + it * 512];
            pk[it] = k4g[tid + it * 512];
        }
    }

    {
        const float4* w4 = (const float4*)(w + base);
        const float4* v4 = (const float4*)(v + base);
        #pragma unroll
        for (int it = 0; it < 4; ++it) {
            int f4 = tid + it * 512;
            int t = f4 >> 4, k0 = (f4 & 15) * 4;
            float4 ww = w4[f4];
            ww.x = fmaxf(ww.x, LOGMIN); ww.y = fmaxf(ww.y, LOGMIN);
            ww.z = fmaxf(ww.z, LOGMIN); ww.w = fmaxf(ww.w, LOGMIN);
            *(float4*)&sm[O_CUM + t * 64 + k0] = ww;
            float4 vv = v4[f4];
            vv.x = f2tf(vv.x); vv.y = f2tf(vv.y); vv.z = f2tf(vv.z); vv.w = f2tf(vv.w);
            *(float4*)&sm[O_V + t * 72 + k0] = vv;
        }
        if (tid < 64) sm[O_U + tid] = u[h * 64 + tid];
    }
    __syncthreads();

    {
        int kq = tid & 63, seg = tid >> 6;
        float run = 0.f;
        #pragma unroll
        for (int tt = 0; tt < 16; ++tt) {
            int idx = (seg * 16 + tt) * 64 + kq;
            run += sm[O_CUM + idx];
            sm[O_CUM + idx] = run;
        }
        sm[O_SEG + seg * 64 + kq] = run;
    }
    __syncthreads();

    {
        int kq = tid & 63, seg = tid >> 6;
        if (seg > 0) {
            float pre = 0.f;
            #pragma unroll
            for (int s = 0; s < 7; ++s)
                if (s < seg) pre += sm[O_SEG + s * 64 + kq];
            #pragma unroll
            for (int tt = 0; tt < 16; ++tt) sm[O_CUM + (seg * 16 + tt) * 64 + kq] += pre;
        } else {
            float ws = 0.f;
            #pragma unroll
            for (int s = 0; s < 8; ++s) ws += sm[O_SEG + s * 64 + kq];
            float ews = __expf(ws);
            sm[O_EWS + kq] = ews;
            g_wse[(bh * N_ + n) * K_ + kq] = ews;
        }
    }
    __syncthreads();

    {
        #pragma unroll
        for (int it = 0; it < 4; ++it) {
            int f4 = tid + it * 512;
            int t = f4 >> 4, k0 = (f4 & 15) * 4;
            float4 rv = pr[it];
            float4 kv = pk[it];
            float4 c4 = *(const float4*)&sm[O_CUM + t * 64 + k0];
            float4 cp4 = (t > 0) ? *(const float4*)&sm[O_CUM + (t - 1) * 64 + k0]
                                 : make_float4(0.f, 0.f, 0.f, 0.f);
            float4 uu = *(const float4*)&sm[O_U + k0];
            float re[4] = {rv.x, rv.y, rv.z, rv.w};
            float ke[4] = {kv.x, kv.y, kv.z, kv.w};
            float ce[4] = {c4.x, c4.y, c4.z, c4.w};
            float cpe[4] = {cp4.x, cp4.y, cp4.z, cp4.w};
            float ue[4] = {uu.x, uu.y, uu.z, uu.w};
            float rwv[4], kkv[4];
            float dpart = 0.f;
            #pragma unroll
            for (int e = 0; e < 4; ++e) {
                rwv[e] = f2tf(re[e] * __expf(cpe[e]));
                kkv[e] = f2tf(ke[e] * __expf(-ce[e]));
                dpart += re[e] * ue[e] * ke[e];
            }
            *(float4*)&sm[O_RW + t * 68 + k0] = make_float4(rwv[0], rwv[1], rwv[2], rwv[3]);
            *(float4*)&sm[O_KK + t * 76 + k0] = make_float4(kkv[0], kkv[1], kkv[2], kkv[3]);
            uint2 hp = make_uint2(packh2(rwv[0], rwv[1]), packh2(rwv[2], rwv[3]));
            *(uint2*)&g_rwi[base + f4 * 4] = hp;
            float dv = dpart;
            #pragma unroll
            for (int s = 1; s < 16; s <<= 1) dv += __shfl_xor_sync(0xffffffffu, dv, s, 16);
            if ((tid & 15) == 0) sm[O_DIAG + t] = dv;
        }
    }
    __syncthreads();

    const int jh = wid >> 3;
    const int widL = wid & 7;
    const int blk = (widL < 4) ? widL : 11 - widL;
    const int i0 = blk * 16;
    int ntmax = (i0 + 16 - jh * 64) >> 3;
    ntmax = ntmax < 0 ? 0 : (ntmax > 8 ? 8 : ntmax);

    float c1[8][4];
    #pragma unroll
    for (int nt = 0; nt < 8; ++nt)
        #pragma unroll
        for (int e = 0; e < 4; ++e) c1[nt][e] = 0.f;

    #pragma unroll
    for (int ks = 0; ks < 8; ++ks) {
        int k0 = ks * 8;
        const float* ar = &sm[O_RW + (i0 + ly) * 68 + k0 + lx];
        uint32_t a0 = FB(ar[0]), a1 = FB(ar[8 * 68]), a2 = FB(ar[4]), a3 = FB(ar[8 * 68 + 4]);
        #pragma unroll
        for (int nt = 0; nt < 8; ++nt) {
            if (nt < ntmax) {
                const float* br = &sm[O_KK + (jh * 64 + nt * 8 + ly) * 76 + k0 + lx];
                mma1688(c1[nt], a0, a1, a2, a3, FB(br[0]), FB(br[4]));
            }
        }
    }

    {
        const int i0k = (wid & 3) * 16, j0c = (wid >> 2) * 16;
        float c3[2][4];
        #pragma unroll
        for (int nt = 0; nt < 2; ++nt)
            #pragma unroll
            for (int e = 0; e < 4; ++e) c3[nt][e] = 0.f;
        #pragma unroll
        for (int ks = 0; ks < 16; ++ks) {
            int k0 = ks * 8;
            const float* ac = &sm[O_KK + (k0 + lx) * 76 + i0k + ly];
            uint32_t a0 = FB(ac[0]), a1 = FB(ac[8]), a2 = FB(ac[4 * 76]), a3 = FB(ac[4 * 76 + 8]);
            #pragma unroll
            for (int nt = 0; nt < 2; ++nt) {
                const float* br = &sm[O_V + (k0 + lx) * 72 + j0c + nt * 8 + ly];
                mma1688(c3[nt], a0, a1, a2, a3, FB(br[0]), FB(br[4 * 72]));
            }
        }
        int wb = bhn * (K_ * K_);
        int il = i0k + ly, ih = il + 8;
        float sl = sm[O_EWS + il], sh = sm[O_EWS + ih];
        #pragma unroll
        for (int nt = 0; nt < 2; ++nt) {
            int jb = j0c + nt * 8 + 2 * lx;
            *(float2*)&g_wkv[wb + il * 64 + jb] = make_float2(c3[nt][0] * sl, c3[nt][1] * sl);
            *(float2*)&g_wkv[wb + ih * 64 + jb] = make_float2(c3[nt][2] * sh, c3[nt][3] * sh);
        }
    }
    __syncthreads();

    float c2[8][4];
    #pragma unroll
    for (int nt = 0; nt < 8; ++nt)
        #pragma unroll
        for (int e = 0; e < 4; ++e) c2[nt][e] = 0.f;

    {
        const int il = i0 + ly, ih = il + 8;
        const int l1 = ly * 4 + (lx >> 1);
        const int l2 = l1 + 2;
        const bool odd = lx & 1;
        #pragma unroll
        for (int nt = 0; nt < 8; ++nt) {
            if (nt < ntmax) {
                int jc = jh * 64 + nt * 8;
                int jcg = jc + 2 * lx;
                float m0 = (jcg     < il) ? f2tf(c1[nt][0]) : 0.f;
                float m1 = (jcg + 1 < il) ? f2tf(c1[nt][1]) : 0.f;
                float m2 = (jcg     < ih) ? f2tf(c1[nt][2]) : 0.f;
                float m3 = (jcg + 1 < ih) ? f2tf(c1[nt][3]) : 0.f;
                float t00 = __shfl_sync(0xffffffffu, m0, l1);
                float t01 = __shfl_sync(0xffffffffu, m1, l1);
                float t20 = __shfl_sync(0xffffffffu, m0, l2);
                float t21 = __shfl_sync(0xffffffffu, m1, l2);
                float t10 = __shfl_sync(0xffffffffu, m2, l1);
                float t11 = __shfl_sync(0xffffffffu, m3, l1);
                float t30 = __shfl_sync(0xffffffffu, m2, l2);
                float t31 = __shfl_sync(0xffffffffu, m3, l2);
                uint32_t a0 = FB(odd ? t01 : t00);
                uint32_t a2 = FB(odd ? t21 : t20);
                uint32_t a1 = FB(odd ? t11 : t10);
                uint32_t a3 = FB(odd ? t31 : t30);
                #pragma unroll
                for (int no = 0; no < 8; ++no) {
                    const float* br = &sm[O_V + (jc + lx) * 72 + no * 8 + ly];
                    mma1688(c2[no], a0, a1, a2, a3, FB(br[0]), FB(br[4 * 72]));
                }
            }
        }
    }

    if (jh == 1 && ntmax > 0) {
        float* pb = &sm[O_RW + (blk - 4) * 1088];
        int jb = 2 * lx;
        #pragma unroll
        for (int nt = 0; nt < 8; ++nt) {
            *(float2*)&pb[ly * 68 + nt * 8 + jb]       = make_float2(c2[nt][0], c2[nt][1]);
            *(float2*)&pb[(ly + 8) * 68 + nt * 8 + jb] = make_float2(c2[nt][2], c2[nt][3]);
        }
    }
    __syncthreads();

    if (jh == 0) {
        const int il = i0 + ly, ih = il + 8;
        const float dgl = sm[O_DIAG + il], dgh = sm[O_DIAG + ih];
        const bool haveP = (blk >= 4);
        const float* pb = &sm[O_RW + (blk - 4) * 1088];
        #pragma unroll
        for (int nt = 0; nt < 8; ++nt) {
            int jb = nt * 8 + 2 * lx;
            float2 pl = make_float2(0.f, 0.f), ph = make_float2(0.f, 0.f);
            if (haveP) {
                pl = *(const float2*)&pb[ly * 68 + jb];
                ph = *(const float2*)&pb[(ly + 8) * 68 + jb];
            }
            float2 vl = *(const float2*)&sm[O_V + il * 72 + jb];
            float2 vh = *(const float2*)&sm[O_V + ih * 72 + jb];
            float o0 = c2[nt][0] + pl.x + dgl * vl.x;
            float o1 = c2[nt][1] + pl.y + dgl * vl.y;
            float o2 = c2[nt][2] + ph.x + dgh * vh.x;
            float o3 = c2[nt][3] + ph.y + dgh * vh.y;
            *(float2*)&out[base + il * 64 + jb] = make_float2(o0, o1);
            *(float2*)&out[base + ih * 64 + jb] = make_float2(o2, o3);
        }
    }
}

// ============ fused scan + inter-chunk (round-8 structure, fp16 rw, out prefetch) ============
// grid: 64 bh x 4 col-slices, 256 threads. Block owns 16 state cols (exact fp32 regs).
#define F_RW0  0         // 128 x 68 floats
#define F_RW1  8704
#define F_ST0  17408     // 64 x 24
#define F_ST1  18944
#define FUSED_FLOATS 20480
#define FUSED_BYTES  (FUSED_FLOATS*4)

__global__ void __launch_bounds__(256)
rwkv_scan_inter(const float* __restrict__ state0, float* __restrict__ out,
                float* __restrict__ outF)
{
    extern __shared__ float sm[];
    const int tid = threadIdx.x;
    const int wid = tid >> 5, lid = tid & 31;
    const int ly = lid >> 2, lx = lid & 3;
    const int bh = blockIdx.x >> 2;
    const int j0c = (blockIdx.x & 3) * 16;
    const int base_bh = bh * (T_ * K_);

    // state ownership: thread -> row kq, cols j0c+jq..+3
    const int kq = tid >> 2;
    const int jq = (tid & 3) * 4;
    float4 st = *(const float4*)&state0[bh * (K_ * K_) + kq * 64 + j0c + jq];

    // staging map for fp16 rw: idx = tid + it*256 (it<4) -> 8 halves
    // t = idx>>3, k0 = (idx&7)*8
    // preload chunk 0
    {
        const uint4* rwh = (const uint4*)(g_rwi + base_bh);
        #pragma unroll
        for (int it = 0; it < 4; ++it) {
            int idx = tid + it * 256;
            int t = idx >> 3, k0 = (idx & 7) * 8;
            uint4 pv = rwh[idx];
            float2 f0 = __half22float2(*(__half2*)&pv.x);
            float2 f1 = __half22float2(*(__half2*)&pv.y);
            float2 f2 = __half22float2(*(__half2*)&pv.z);
            float2 f3 = __half22float2(*(__half2*)&pv.w);
            *(float4*)&sm[F_RW0 + t * 68 + k0]     = make_float4(f0.x, f0.y, f1.x, f1.y);
            *(float4*)&sm[F_RW0 + t * 68 + k0 + 4] = make_float4(f2.x, f2.y, f3.x, f3.y);
        }
        float4 sr = make_float4(f2tf(st.x), f2tf(st.y), f2tf(st.z), f2tf(st.w));
        *(float4*)&sm[F_ST0 + kq * 24 + jq] = sr;
    }
    __syncthreads();

    const int i0 = wid * 16;

    for (int n = 0; n < N_; ++n) {
        const int cur  = (n & 1) ? F_RW1 : F_RW0;
        const int curS = (n & 1) ? F_ST1 : F_ST0;
        const int nxt  = (n & 1) ? F_RW0 : F_RW1;
        const int nxtS = (n & 1) ? F_ST0 : F_ST1;

        // prefetch next rw chunk (fp16, 4 uint4 regs)
        uint4 pf[4];
        {
            int np = (n < 15) ? n + 1 : 15;
            const uint4* rwh = (const uint4*)(g_rwi + base_bh + np * (CH_ * K_));
            #pragma unroll
            for (int it = 0; it < 4; ++it) pf[it] = rwh[tid + it * 256];
        }
        // prefetch wkv + ews for state update
        const int cb = bh * N_ + n;
        float4 wkvv = *(const float4*)&g_wkv[cb * (K_ * K_) + kq * 64 + j0c + jq];
        float ews = __ldg(&g_wse[cb * K_ + kq]);

        // prefetch out tile (RMW load overlaps MMAs)
        float* ob = out + base_bh + n * (CH_ * K_);
        const int il = i0 + ly, ih = il + 8;
        float2 o_l[2], o_h[2];
        #pragma unroll
        for (int nt = 0; nt < 2; ++nt) {
            int jb = j0c + nt * 8 + 2 * lx;
            o_l[nt] = *(const float2*)&ob[il * 64 + jb];
            o_h[nt] = *(const float2*)&ob[ih * 64 + jb];
        }

        // MMA: out_tile(16x16) += rw(16x64) @ state(64x16)
        float c[2][4];
        #pragma unroll
        for (int nt = 0; nt < 2; ++nt)
            #pragma unroll
            for (int e = 0; e < 4; ++e) c[nt][e] = 0.f;

        #pragma unroll
        for (int ks = 0; ks < 8; ++ks) {
            int k0 = ks * 8;
            const float* ar = &sm[cur + (i0 + ly) * 68 + k0 + lx];
            uint32_t a0 = FB(ar[0]), a1 = FB(ar[8 * 68]), a2 = FB(ar[4]), a3 = FB(ar[8 * 68 + 4]);
            #pragma unroll
            for (int nt = 0; nt < 2; ++nt) {
                const float* br = &sm[curS + (k0 + lx) * 24 + nt * 8 + ly];
                mma1688(c[nt], a0, a1, a2, a3, FB(br[0]), FB(br[4 * 24]));
            }
        }

        // out RMW store
        #pragma unroll
        for (int nt = 0; nt < 2; ++nt) {
            int jb = j0c + nt * 8 + 2 * lx;
            o_l[nt].x += c[nt][0]; o_l[nt].y += c[nt][1];
            o_h[nt].x += c[nt][2]; o_h[nt].y += c[nt][3];
            *(float2*)&ob[il * 64 + jb] = o_l[nt];
            *(float2*)&ob[ih * 64 + jb] = o_h[nt];
        }

        // state update (exact fp32)
        st.x = fmaf(st.x, ews, wkvv.x);
        st.y = fmaf(st.y, ews, wkvv.y);
        st.z = fmaf(st.z, ews, wkvv.z);
        st.w = fmaf(st.w, ews, wkvv.w);

        if (n < 15) {
            #pragma unroll
            for (int it = 0; it < 4; ++it) {
                int idx = tid + it * 256;
                int t = idx >> 3, k0 = (idx & 7) * 8;
                uint4 pv = pf[it];
                float2 f0 = __half22float2(*(__half2*)&pv.x);
                float2 f1 = __half22float2(*(__half2*)&pv.y);
                float2 f2 = __half22float2(*(__half2*)&pv.z);
                float2 f3 = __half22float2(*(__half2*)&pv.w);
                *(float4*)&sm[nxt + t * 68 + k0]     = make_float4(f0.x, f0.y, f1.x, f1.y);
                *(float4*)&sm[nxt + t * 68 + k0 + 4] = make_float4(f2.x, f2.y, f3.x, f3.y);
            }
            float4 sr = make_float4(f2tf(st.x), f2tf(st.y), f2tf(st.z), f2tf(st.w));
            *(float4*)&sm[nxtS + kq * 24 + jq] = sr;
            __syncthreads();
        }
    }

    // final state (exact)
    *(float4*)&outF[bh * (K_ * K_) + kq * 64 + j0c + jq] = st;
}

extern "C" void kernel_launch(void* const* d_in, const int* in_sizes, int n_in,
                              void* d_out, int out_size)
{
    (void)in_sizes; (void)n_in; (void)out_size;
    const float* r  = (const float*)d_in[0];
    const float* k  = (const float*)d_in[1];
    const float* v  = (const float*)d_in[2];
    const float* w  = (const float*)d_in[3];
    const float* u  = (const float*)d_in[4];
    const float* s0 = (const float*)d_in[5];
    float* out  = (float*)d_out;
    float* outF = out + OUT_ELEMS;

    cudaFuncSetAttribute(rwkv_phase1, cudaFuncAttributeMaxDynamicSharedMemorySize, SMEM1_BYTES);
    cudaFuncSetAttribute(rwkv_scan_inter, cudaFuncAttributeMaxDynamicSharedMemorySize, FUSED_BYTES);

    rwkv_phase1<<<BH_ * N_, 512, SMEM1_BYTES>>>(r, k, v, w, u, out);
    rwkv_scan_inter<<<BH_ * 4, 256, FUSED_BYTES>>>(s0, out, outF);
}